// round 1
// baseline (speedup 1.0000x reference)
#include <cuda_runtime.h>
#include <cuda_bf16.h>
#include <cstdint>

// Problem constants (from reference): B=1024, S=200, D=64, C=256
// Inputs (metadata order): rq_item_embeddings f32 [B,S,D], labels i32 [B,S], attention_mask i32 [B,S]
// Outputs concatenated into d_out (float32):
//   [0 .. B*C*D)              cluster_emb
//   [B*C*D .. B*C*D + B*C*S)  cluster_mask (0.0f / 1.0f)

namespace {
constexpr int B = 1024;
constexpr int S = 200;
constexpr int D = 64;
constexpr int C = 256;

constexpr int SMEM_LAB_BYTES   = 1024;            // 200 ints, padded
constexpr int SMEM_ACC_BYTES   = C * D * 4;       // 65536
constexpr int SMEM_CNT_BYTES   = C * 4;           // 1024
constexpr int SMEM_TOTAL = SMEM_LAB_BYTES + SMEM_ACC_BYTES + SMEM_CNT_BYTES;  // 67584
}

__global__ __launch_bounds__(256) void s3rec_cluster_kernel(
    const float*  __restrict__ x,       // [B,S,D]
    const int*    __restrict__ labels,  // [B,S]
    const int*    __restrict__ amask,   // [B,S]
    float*        __restrict__ out)
{
    extern __shared__ char smem[];
    int*   lab    = reinterpret_cast<int*>(smem);
    float* acc    = reinterpret_cast<float*>(smem + SMEM_LAB_BYTES);
    int*   counts = reinterpret_cast<int*>(smem + SMEM_LAB_BYTES + SMEM_ACC_BYTES);

    const int b   = blockIdx.x;
    const int tid = threadIdx.x;

    // 1) fused label+mask load: lab[s] = mask ? label : -1
    for (int s = tid; s < S; s += 256) {
        int m = amask[b * S + s];
        lab[s] = m ? labels[b * S + s] : -1;
    }
    // zero accumulators
    for (int i = tid; i < C * D; i += 256) acc[i] = 0.0f;
    if (tid < C) counts[tid] = 0;
    __syncthreads();

    // 2) scatter-accumulate: warp per s, lane covers 2 of D=64 floats
    {
        const int w    = tid >> 5;
        const int lane = tid & 31;
        for (int s = w; s < S; s += 8) {
            int c = lab[s];
            if (c >= 0) {
                if (lane == 0) atomicAdd(&counts[c], 1);
                const float2 v = reinterpret_cast<const float2*>(
                    x + ((size_t)b * S + s) * D)[lane];
                atomicAdd(&acc[c * D + lane * 2],     v.x);
                atomicAdd(&acc[c * D + lane * 2 + 1], v.y);
            }
        }
    }
    __syncthreads();

    // 3a) cluster_emb out: acc * (counts>0 ? 1/counts : 0), float4 streaming
    float* embOut = out + (size_t)b * C * D;
    #pragma unroll 4
    for (int i = tid; i < (C * D) / 4; i += 256) {
        float4 v = reinterpret_cast<float4*>(acc)[i];
        int   c   = i >> 4;  // (i*4)/64
        int   cnt = counts[c];
        float inv = (cnt > 0) ? (1.0f / (float)cnt) : 0.0f;
        v.x *= inv; v.y *= inv; v.z *= inv; v.w *= inv;
        reinterpret_cast<float4*>(embOut)[i] = v;
    }

    // 3b) cluster_mask out: one-hot compare against smem labels, float4 streaming
    float* maskOut = out + (size_t)B * C * D + (size_t)b * C * S;
    #pragma unroll 2
    for (int i = tid; i < (C * S) / 4; i += 256) {
        const int c  = i / (S / 4);
        const int s0 = (i % (S / 4)) * 4;
        float4 v;
        v.x = (lab[s0 + 0] == c) ? 1.0f : 0.0f;
        v.y = (lab[s0 + 1] == c) ? 1.0f : 0.0f;
        v.z = (lab[s0 + 2] == c) ? 1.0f : 0.0f;
        v.w = (lab[s0 + 3] == c) ? 1.0f : 0.0f;
        reinterpret_cast<float4*>(maskOut)[i] = v;
    }
}

extern "C" void kernel_launch(void* const* d_in, const int* in_sizes, int n_in,
                              void* d_out, int out_size)
{
    const float* x      = (const float*)d_in[0];
    const int*   labels = (const int*)d_in[1];
    const int*   amask  = (const int*)d_in[2];
    float*       out    = (float*)d_out;

    cudaFuncSetAttribute(s3rec_cluster_kernel,
                         cudaFuncAttributeMaxDynamicSharedMemorySize, SMEM_TOTAL);
    s3rec_cluster_kernel<<<B, 256, SMEM_TOTAL>>>(x, labels, amask, out);
}